// round 1
// baseline (speedup 1.0000x reference)
#include <cuda_runtime.h>
#include <math.h>

#define BB 64
#define LL 64
#define HH 512
#define NSTATE (BB*LL*HH)   // 2,097,152 floats = 8 MB

// Scratch state (allocation-free rule: __device__ globals)
__device__ float g_h[2][NSTATE];
__device__ float g_c[2][NSTATE];
__device__ float g_nh[NSTATE];
__device__ float g_nc[NSTATE];
__device__ int   g_sel[BB];

__device__ __forceinline__ float sigm(float x) { return 1.0f / (1.0f + expf(-x)); }

// ---------------------------------------------------------------------------
// Word GEMM: state = x @ w_word^T + b_word ; h = state[:, :512], c = state[:, 512:]
// M = B*L = 4096, K = 512, N = 1024
// ---------------------------------------------------------------------------
__global__ __launch_bounds__(256) void word_gemm(
    const float* __restrict__ x, const float* __restrict__ w,
    const float* __restrict__ bias)
{
    __shared__ float As[64][33];
    __shared__ float Ws[64][33];
    int tid = threadIdx.x;
    int tx = tid & 15, ty = tid >> 4;
    int m0 = blockIdx.y * 64;
    int c0 = blockIdx.x * 64;
    float acc[4][4] = {};

    for (int k0 = 0; k0 < 512; k0 += 32) {
        #pragma unroll
        for (int t = tid; t < 64 * 32; t += 256) {
            int r = t >> 5, kk = t & 31;
            As[r][kk] = x[(m0 + r) * 512 + k0 + kk];
            Ws[r][kk] = w[(c0 + r) * 512 + k0 + kk];
        }
        __syncthreads();
        #pragma unroll
        for (int kk = 0; kk < 32; kk++) {
            float a[4], b[4];
            #pragma unroll
            for (int r = 0; r < 4; r++) a[r] = As[ty * 4 + r][kk];
            #pragma unroll
            for (int cc = 0; cc < 4; cc++) b[cc] = Ws[tx * 4 + cc][kk];
            #pragma unroll
            for (int r = 0; r < 4; r++)
                #pragma unroll
                for (int cc = 0; cc < 4; cc++)
                    acc[r][cc] += a[r] * b[cc];
        }
        __syncthreads();
    }
    #pragma unroll
    for (int r = 0; r < 4; r++) {
        int m = m0 + ty * 4 + r;
        #pragma unroll
        for (int cc = 0; cc < 4; cc++) {
            int col = c0 + tx * 4 + cc;
            float v = acc[r][cc] + bias[col];
            if (col < 512) g_h[0][m * 512 + col] = v;
            else           g_c[0][m * 512 + col - 512] = v;
        }
    }
}

// ---------------------------------------------------------------------------
// Compose: v = [h_j, h_{j+1}] @ w_comp^T + b_comp (5 gates) -> new_h, new_c
// M = B*n rows, K = 1024, block tile = 128 rows x 16 h-cols x 5 gates
// 256 threads: thread = (tx in 0..15 -> h, ty in 0..15 -> 8 rows), acc[8][5]
// ---------------------------------------------------------------------------
__global__ __launch_bounds__(256) void compose(
    const float* __restrict__ wcomp, const float* __restrict__ bcomp,
    int p, int n)
{
    __shared__ float As[128][33];
    __shared__ float Ws[5][16][33];

    int tid = threadIdx.x;
    int tx = tid & 15, ty = tid >> 4;
    int h0 = blockIdx.x * 16;
    int m0 = blockIdx.y * 128;
    int M  = BB * n;

    const float* __restrict__ hbuf = g_h[p];
    const float* __restrict__ cbuf = g_c[p];

    // A-load role: element idx = tid + 256*t over 128x32 tile
    int lr   = tid >> 5;   // 0..7
    int kkld = tid & 31;
    int abase[16];
    #pragma unroll
    for (int t = 0; t < 16; t++) {
        int row = m0 + lr + 8 * t;
        if (row < M) {
            int b = row / n;
            int j = row - b * n;
            // concat(h[b][j], h[b][j+1]) is 1024 contiguous floats
            abase[t] = (b * 64 + j) * 512;
        } else {
            abase[t] = -1;
        }
    }

    float acc[8][5] = {};

    for (int k0 = 0; k0 < 1024; k0 += 32) {
        #pragma unroll
        for (int t = 0; t < 16; t++)
            As[lr + 8 * t][kkld] = (abase[t] >= 0) ? hbuf[abase[t] + k0 + kkld] : 0.0f;
        #pragma unroll
        for (int t = 0; t < 10; t++) {
            int idx = tid + 256 * t;
            int g   = idx >> 9;
            int rem = idx & 511;
            int hh  = rem >> 5;
            int kk  = rem & 31;
            Ws[g][hh][kk] = wcomp[(g * 512 + h0 + hh) * 1024 + k0 + kk];
        }
        __syncthreads();
        #pragma unroll
        for (int kk = 0; kk < 32; kk++) {
            float wv[5];
            #pragma unroll
            for (int g = 0; g < 5; g++) wv[g] = Ws[g][tx][kk];
            #pragma unroll
            for (int r = 0; r < 8; r++) {
                float av = As[ty * 8 + r][kk];
                #pragma unroll
                for (int g = 0; g < 5; g++) acc[r][g] += av * wv[g];
            }
        }
        __syncthreads();
    }

    int hg = h0 + tx;
    float bi  = bcomp[hg];
    float bfl = bcomp[512 + hg];
    float bfr = bcomp[1024 + hg];
    float bu  = bcomp[1536 + hg];
    float bo  = bcomp[2048 + hg];

    #pragma unroll
    for (int r = 0; r < 8; r++) {
        int row = m0 + ty * 8 + r;
        if (row >= M) continue;
        int b = row / n;
        int j = row - b * n;
        int base = (b * 64 + j) * 512;
        float cl = cbuf[base + hg];
        float cr = cbuf[base + 512 + hg];
        float ig = sigm(acc[r][0] + bi);
        float fl = sigm(acc[r][1] + bfl + 1.0f);
        float fr = sigm(acc[r][2] + bfr + 1.0f);
        float u  = tanhf(acc[r][3] + bu);
        float og = sigm(acc[r][4] + bo);
        float cn = cl * fl + cr * fr + u * ig;
        float hn = og * tanhf(cn);
        g_nh[base + hg] = hn;
        g_nc[base + hg] = cn;
    }
}

// ---------------------------------------------------------------------------
// Select: per-batch cw = new_h . q, masked argmax (first max, like jnp.argmax)
// sel = -2 encodes "sequence done -> plain truncation"
// ---------------------------------------------------------------------------
__global__ __launch_bounds__(256) void select_k(
    const float* __restrict__ q, const int* __restrict__ length, int i, int n)
{
    int b = blockIdx.x;
    int len = length[b];
    if (i + 1 >= len) {               // done == 0: no composition this step
        if (threadIdx.x == 0) g_sel[b] = -2;
        return;
    }
    __shared__ float cw[64];
    int warp = threadIdx.x >> 5, lane = threadIdx.x & 31;
    for (int j = warp; j < n; j += 8) {
        const float* row = &g_nh[(b * 64 + j) * 512];
        float s = 0.0f;
        #pragma unroll
        for (int t = 0; t < 16; t++) {
            int k = lane + 32 * t;
            s += row[k] * q[k];
        }
        #pragma unroll
        for (int o = 16; o > 0; o >>= 1) s += __shfl_xor_sync(0xffffffffu, s, o);
        if (lane == 0) cw[j] = s;
    }
    __syncthreads();
    if (threadIdx.x == 0) {
        float best = -3.0e9f;
        int bi = 0;
        for (int j = 0; j < n; j++) {
            float v = (i + 1 + j < len) ? cw[j] : -1.0e9f;
            if (v > best) { best = v; bi = j; }
        }
        g_sel[b] = bi;
    }
}

// ---------------------------------------------------------------------------
// Recombine: h_next[j] = (j<sel? h[j] : j==sel? new_h[j] : h[j+1]); done->copy
// One block per (b, j) row; float4 moves of h and c.
// ---------------------------------------------------------------------------
__global__ __launch_bounds__(128) void recomb(int p, int n)
{
    int row = blockIdx.x;
    int b = row / n;
    int j = row - b * n;
    int s = g_sel[b];
    int tid = threadIdx.x;
    int dst = (b * 64 + j) * 512;

    const float4 *sh, *sc;
    if (s >= 0 && j == s) {
        sh = (const float4*)&g_nh[dst];
        sc = (const float4*)&g_nc[dst];
    } else {
        int jj = (s >= 0 && j > s) ? (j + 1) : j;
        int src = (b * 64 + jj) * 512;
        sh = (const float4*)&g_h[p][src];
        sc = (const float4*)&g_c[p][src];
    }
    ((float4*)&g_h[p ^ 1][dst])[tid] = sh[tid];
    ((float4*)&g_c[p ^ 1][dst])[tid] = sc[tid];
}

// ---------------------------------------------------------------------------
// Finalize: out = concat(h[:,0,:], c[:,0,:])
// ---------------------------------------------------------------------------
__global__ __launch_bounds__(512) void finalize(float* __restrict__ out, int p)
{
    int b = blockIdx.x;
    int k = threadIdx.x;
    out[b * 512 + k]                = g_h[p][(b * 64) * 512 + k];
    out[BB * 512 + b * 512 + k]     = g_c[p][(b * 64) * 512 + k];
}

// ---------------------------------------------------------------------------
extern "C" void kernel_launch(void* const* d_in, const int* in_sizes, int n_in,
                              void* d_out, int out_size)
{
    const float* x      = (const float*)d_in[0];
    const int*   length = (const int*)  d_in[1];
    const float* w_word = (const float*)d_in[2];
    const float* b_word = (const float*)d_in[3];
    const float* w_comp = (const float*)d_in[4];
    const float* b_comp = (const float*)d_in[5];
    const float* q      = (const float*)d_in[6];
    float* out = (float*)d_out;

    dim3 wg(1024 / 64, 4096 / 64);
    word_gemm<<<wg, 256>>>(x, w_word, b_word);

    for (int i = 0; i < LL - 1; i++) {
        int n = (LL - 1) - i;     // number of candidate compositions
        int p = i & 1;
        dim3 cg(HH / 16, (BB * n + 127) / 128);
        compose<<<cg, 256>>>(w_comp, b_comp, p, n);
        select_k<<<BB, 256>>>(q, length, i, n);
        recomb<<<BB * n, 128>>>(p, n);
    }
    finalize<<<BB, 512>>>(out, (LL - 1) & 1);
}

// round 2
// speedup vs baseline: 3.2019x; 3.2019x over previous
#include <cuda_runtime.h>
#include <math.h>

#define BB 64
#define LL 64
#define HH 512
#define NPAIR0 63
#define NSTATE (BB*LL*HH)   // 8 MB per array

// Physical-slot state; slots are stable, only the merged slot is rewritten.
__device__ float g_h[NSTATE];
__device__ float g_c[NSTATE];
// Pair-compose results keyed by LEFT leaf's physical slot: (b*64+slotL)*512
__device__ float g_nh[NSTATE];
__device__ float g_nc[NSTATE];
__device__ float g_cw[BB*64];   // cw keyed by left slot
__device__ int   g_idx[BB*64];  // logical leaf j -> physical slot
__device__ int2  g_rows[BB*2];  // per batch, up to 2 fresh pair rows {keyL, keyR}; x=-1 invalid

__device__ __forceinline__ float sigm(float x){ return 1.0f/(1.0f+expf(-x)); }

// packed fp32x2 FMA: 2 MACs per instruction (scalar FFMA is half-rate on sm_103a)
__device__ __forceinline__ void ffma2(float2 &acc, float2 a, float2 b){
    asm("fma.rn.f32x2 %0, %1, %2, %0;"
        : "+l"(reinterpret_cast<unsigned long long&>(acc))
        : "l"(reinterpret_cast<unsigned long long&>(a)),
          "l"(reinterpret_cast<unsigned long long&>(b)));
}

// ---------------------------------------------------------------------------
// Word GEMM: state = x @ w_word^T + b_word ; h = state[:,:512], c = state[:,512:]
// ---------------------------------------------------------------------------
__global__ __launch_bounds__(256) void word_gemm(
    const float* __restrict__ x, const float* __restrict__ w,
    const float* __restrict__ bias)
{
    __shared__ float As[64][33];
    __shared__ float Ws[64][33];
    int tid = threadIdx.x;
    int tx = tid & 15, ty = tid >> 4;
    int m0 = blockIdx.y * 64;
    int c0 = blockIdx.x * 64;
    float acc[4][4] = {};

    for (int k0 = 0; k0 < 512; k0 += 32) {
        #pragma unroll
        for (int t = tid; t < 64 * 32; t += 256) {
            int r = t >> 5, kk = t & 31;
            As[r][kk] = x[(m0 + r) * 512 + k0 + kk];
            Ws[r][kk] = w[(c0 + r) * 512 + k0 + kk];
        }
        __syncthreads();
        #pragma unroll
        for (int kk = 0; kk < 32; kk++) {
            float a[4], b[4];
            #pragma unroll
            for (int r = 0; r < 4; r++) a[r] = As[ty * 4 + r][kk];
            #pragma unroll
            for (int cc = 0; cc < 4; cc++) b[cc] = Ws[tx * 4 + cc][kk];
            #pragma unroll
            for (int r = 0; r < 4; r++)
                #pragma unroll
                for (int cc = 0; cc < 4; cc++)
                    acc[r][cc] += a[r] * b[cc];
        }
        __syncthreads();
    }
    #pragma unroll
    for (int r = 0; r < 4; r++) {
        int m = m0 + ty * 4 + r;
        #pragma unroll
        for (int cc = 0; cc < 4; cc++) {
            int col = c0 + tx * 4 + cc;
            float v = acc[r][cc] + bias[col];
            if (col < 512) g_h[m * 512 + col] = v;
            else           g_c[m * 512 + col - 512] = v;
        }
    }
}

__global__ void init_idx(){
    int t = blockIdx.x * blockDim.x + threadIdx.x;
    if (t < BB * 64) g_idx[t] = t & 63;
    if (t < BB * 2)  g_rows[t] = make_int2(-1, -1);
}

// ---------------------------------------------------------------------------
// Full compose for iteration 0: all 63 pairs per batch. f32x2 inner loop.
// Tile: 128 rows x (8 hcols x 5 gates). 256 thr: tx=hh(8), ty=0..31 (4 rows).
// ---------------------------------------------------------------------------
__global__ __launch_bounds__(256) void compose_full(
    const float* __restrict__ wcomp, const float* __restrict__ bcomp)
{
    __shared__ float As[128][34];
    __shared__ float Ws[5][8][34];
    const int tid = threadIdx.x;
    const int tx = tid & 7, ty = tid >> 3;
    const int h0 = blockIdx.x * 8;
    const int m0 = blockIdx.y * 128;
    const int M  = BB * NPAIR0;   // 4032

    const int lr = tid >> 5, kkld = tid & 31;
    int abase[16];
    #pragma unroll
    for (int t = 0; t < 16; t++) {
        int row = m0 + lr + 8 * t;
        if (row < M) { int b = row / 63; int j = row - b * 63; abase[t] = (b * 64 + j) * 512; }
        else abase[t] = -1;
    }

    float2 acc[4][5];
    #pragma unroll
    for (int r = 0; r < 4; r++)
        #pragma unroll
        for (int g = 0; g < 5; g++) acc[r][g] = make_float2(0.f, 0.f);

    for (int k0 = 0; k0 < 1024; k0 += 32) {
        #pragma unroll
        for (int t = 0; t < 16; t++)
            As[lr + 8 * t][kkld] = (abase[t] >= 0) ? g_h[abase[t] + k0 + kkld] : 0.f;
        #pragma unroll
        for (int t = 0; t < 5; t++) {
            int idx = tid + 256 * t;          // 1280 elems exactly
            int g = idx >> 8, rem = idx & 255, hh = rem >> 5, kk = rem & 31;
            Ws[g][hh][kk] = wcomp[(g * 512 + h0 + hh) * 1024 + k0 + kk];
        }
        __syncthreads();
        #pragma unroll
        for (int k2 = 0; k2 < 16; k2++) {
            float2 wv[5];
            #pragma unroll
            for (int g = 0; g < 5; g++) wv[g] = ((const float2*)Ws[g][tx])[k2];
            #pragma unroll
            for (int r = 0; r < 4; r++) {
                float2 av = ((const float2*)As[ty * 4 + r])[k2];
                #pragma unroll
                for (int g = 0; g < 5; g++) ffma2(acc[r][g], av, wv[g]);
            }
        }
        __syncthreads();
    }

    int hg = h0 + tx;
    float bi  = bcomp[hg],        bfl = bcomp[512 + hg], bfr = bcomp[1024 + hg];
    float bu  = bcomp[1536 + hg], bo  = bcomp[2048 + hg];
    #pragma unroll
    for (int r = 0; r < 4; r++) {
        int row = m0 + ty * 4 + r;
        if (row >= M) continue;
        int b = row / 63, j = row - b * 63;
        int base = (b * 64 + j) * 512;
        float cl = g_c[base + hg], cr = g_c[base + 512 + hg];
        float vi  = acc[r][0].x + acc[r][0].y + bi;
        float vfl = acc[r][1].x + acc[r][1].y + bfl + 1.f;
        float vfr = acc[r][2].x + acc[r][2].y + bfr + 1.f;
        float vu  = acc[r][3].x + acc[r][3].y + bu;
        float vo  = acc[r][4].x + acc[r][4].y + bo;
        float cn = cl * sigm(vfl) + cr * sigm(vfr) + tanhf(vu) * sigm(vi);
        float hn = sigm(vo) * tanhf(cn);
        g_nh[base + hg] = hn;
        g_nc[base + hg] = cn;
    }
}

// cw for all initial pair keys (slot j = 0..62)
__global__ __launch_bounds__(256) void cw_full(const float* __restrict__ q){
    int b = blockIdx.x;
    int warp = threadIdx.x >> 5, lane = threadIdx.x & 31;
    for (int j = warp; j < 63; j += 8) {
        const float* row = &g_nh[(b * 64 + j) * 512];
        float s = 0.f;
        #pragma unroll
        for (int t = 0; t < 16; t++) s += row[lane + 32 * t] * q[lane + 32 * t];
        #pragma unroll
        for (int o = 16; o > 0; o >>= 1) s += __shfl_xor_sync(0xffffffffu, s, o);
        if (lane == 0) g_cw[b * 64 + j] = s;
    }
}

// ---------------------------------------------------------------------------
// select_update: refresh cw for rows composed last iter, argmax (first-max,
// masked), merge: copy nh/nc -> h/c at merged slot, shift idx, emit new rows.
// ---------------------------------------------------------------------------
__global__ __launch_bounds__(256) void select_update(
    const int* __restrict__ length, const float* __restrict__ q, int i, int n)
{
    int b = blockIdx.x, tid = threadIdx.x;
    __shared__ int sh_idx[64];
    __shared__ int sh_s;
    __shared__ float red[8];
    if (tid < 64) sh_idx[tid] = g_idx[b * 64 + tid];

    int warp = tid >> 5, lane = tid & 31;
    // refresh cw for the <=2 keys recomputed by compose_inc last iteration
    #pragma unroll
    for (int t = 0; t < 2; t++) {
        int key = g_rows[b * 2 + t].x;   // block-uniform
        if (key >= 0) {
            const float* row = &g_nh[key * 512];
            float s = 0.f;
            #pragma unroll
            for (int u = 0; u < 2; u++) { int k = tid + 256 * u; s += row[k] * q[k]; }
            #pragma unroll
            for (int o = 16; o > 0; o >>= 1) s += __shfl_xor_sync(0xffffffffu, s, o);
            if (lane == 0) red[warp] = s;
            __syncthreads();
            if (tid == 0) {
                float tot = 0.f;
                #pragma unroll
                for (int w = 0; w < 8; w++) tot += red[w];
                g_cw[key] = tot;
            }
            __syncthreads();
        }
    }
    __syncthreads();

    if (tid == 0) {
        int len = length[b];
        int s;
        if (i + 1 >= len) s = -2;                 // done==0: plain truncation
        else if (n == 1) s = 0;                   // last iter, no selection
        else {
            float best = -2e9f; int bi = 0;
            for (int j = 0; j < n; j++) {
                float v = (i + 1 + j < len) ? g_cw[b * 64 + sh_idx[j]] : -1e9f;
                if (v > best) { best = v; bi = j; }
            }
            s = bi;
        }
        sh_s = s;
        int2 ra = make_int2(-1, -1), rb = make_int2(-1, -1);
        if (s >= 0 && i < LL - 2) {
            if (s >= 1)     ra = make_int2(b * 64 + sh_idx[s - 1], b * 64 + sh_idx[s]);
            if (s <= n - 2) rb = make_int2(b * 64 + sh_idx[s],     b * 64 + sh_idx[s + 2]);
        }
        g_rows[b * 2 + 0] = ra;
        g_rows[b * 2 + 1] = rb;
    }
    __syncthreads();
    int s = sh_s;
    if (s >= 0) {
        int slot = sh_idx[s];
        int base = (b * 64 + slot) * 512;
        // merged leaf value = compose result of pair s (keyed at its left slot)
        ((float2*)&g_h[base])[tid] = ((const float2*)&g_nh[base])[tid];
        ((float2*)&g_c[base])[tid] = ((const float2*)&g_nc[base])[tid];
        // remove logical leaf s+1
        if (tid >= s + 1 && tid <= n - 1) g_idx[b * 64 + tid] = sh_idx[tid + 1];
    }
}

// ---------------------------------------------------------------------------
// Incremental compose: <=128 fresh rows (2/batch). 128 blocks, hh tile = 4.
// 256 thr: tx=hh(4), ty=0..63 (2 rows). f32x2 inner loop.
// ---------------------------------------------------------------------------
__global__ __launch_bounds__(256) void compose_inc(
    const float* __restrict__ wcomp, const float* __restrict__ bcomp)
{
    __shared__ float As[128][34];
    __shared__ float Ws[5][4][34];
    __shared__ int2 rinfo[128];
    const int tid = threadIdx.x;
    const int tx = tid & 3, ty = tid >> 2;
    const int h0 = blockIdx.x * 4;

    if (tid < 128) rinfo[tid] = g_rows[tid];
    __syncthreads();

    const int rowload = tid >> 4;   // 0..15
    const int kk2 = tid & 15;       // float2 index within 32-wide k chunk

    float2 acc[2][5];
    #pragma unroll
    for (int r = 0; r < 2; r++)
        #pragma unroll
        for (int g = 0; g < 5; g++) acc[r][g] = make_float2(0.f, 0.f);

    for (int k0 = 0; k0 < 1024; k0 += 32) {
        #pragma unroll
        for (int t = 0; t < 8; t++) {
            int row = rowload + 16 * t;
            int2 ri = rinfo[row];
            int k = k0 + kk2 * 2;
            float2 v = make_float2(0.f, 0.f);
            if (ri.x >= 0) {
                int src = (k < 512) ? (ri.x * 512 + k) : (ri.y * 512 + k - 512);
                v = *(const float2*)&g_h[src];
            }
            ((float2*)As[row])[kk2] = v;
        }
        #pragma unroll
        for (int t = 0; t < 3; t++) {
            int idx = tid + 256 * t;
            if (idx < 640) {
                int g = idx >> 7, rem = idx & 127, hh = rem >> 5, kk = rem & 31;
                Ws[g][hh][kk] = wcomp[(g * 512 + h0 + hh) * 1024 + k0 + kk];
            }
        }
        __syncthreads();
        #pragma unroll
        for (int k2 = 0; k2 < 16; k2++) {
            float2 wv[5];
            #pragma unroll
            for (int g = 0; g < 5; g++) wv[g] = ((const float2*)Ws[g][tx])[k2];
            #pragma unroll
            for (int r = 0; r < 2; r++) {
                float2 av = ((const float2*)As[ty * 2 + r])[k2];
                #pragma unroll
                for (int g = 0; g < 5; g++) ffma2(acc[r][g], av, wv[g]);
            }
        }
        __syncthreads();
    }

    int hg = h0 + tx;
    float bi  = bcomp[hg],        bfl = bcomp[512 + hg], bfr = bcomp[1024 + hg];
    float bu  = bcomp[1536 + hg], bo  = bcomp[2048 + hg];
    #pragma unroll
    for (int r = 0; r < 2; r++) {
        int row = ty * 2 + r;
        int2 ri = rinfo[row];
        if (ri.x < 0) continue;
        float cl = g_c[ri.x * 512 + hg], cr = g_c[ri.y * 512 + hg];
        float vi  = acc[r][0].x + acc[r][0].y + bi;
        float vfl = acc[r][1].x + acc[r][1].y + bfl + 1.f;
        float vfr = acc[r][2].x + acc[r][2].y + bfr + 1.f;
        float vu  = acc[r][3].x + acc[r][3].y + bu;
        float vo  = acc[r][4].x + acc[r][4].y + bo;
        float cn = cl * sigm(vfl) + cr * sigm(vfr) + tanhf(vu) * sigm(vi);
        float hn = sigm(vo) * tanhf(cn);
        g_nh[ri.x * 512 + hg] = hn;
        g_nc[ri.x * 512 + hg] = cn;
    }
}

__global__ __launch_bounds__(512) void finalize(float* __restrict__ out){
    int b = blockIdx.x, k = threadIdx.x;
    int slot = g_idx[b * 64];   // logical leaf 0's slot
    out[b * 512 + k]            = g_h[(b * 64 + slot) * 512 + k];
    out[BB * 512 + b * 512 + k] = g_c[(b * 64 + slot) * 512 + k];
}

// ---------------------------------------------------------------------------
extern "C" void kernel_launch(void* const* d_in, const int* in_sizes, int n_in,
                              void* d_out, int out_size)
{
    const float* x      = (const float*)d_in[0];
    const int*   length = (const int*)  d_in[1];
    const float* w_word = (const float*)d_in[2];
    const float* b_word = (const float*)d_in[3];
    const float* w_comp = (const float*)d_in[4];
    const float* b_comp = (const float*)d_in[5];
    const float* q      = (const float*)d_in[6];
    float* out = (float*)d_out;

    word_gemm<<<dim3(16, 64), 256>>>(x, w_word, b_word);
    init_idx<<<16, 256>>>();
    compose_full<<<dim3(64, 32), 256>>>(w_comp, b_comp);
    cw_full<<<BB, 256>>>(q);

    for (int i = 0; i < LL - 1; i++) {
        int n = LL - 1 - i;
        select_update<<<BB, 256>>>(length, q, i, n);
        if (i < LL - 2) compose_inc<<<128, 256>>>(w_comp, b_comp);
    }
    finalize<<<BB, 512>>>(out);
}

// round 3
// speedup vs baseline: 6.1787x; 1.9297x over previous
#include <cuda_runtime.h>
#include <math.h>

#define BB 64
#define LL 64
#define HH 512
#define NPAIR0 63
#define NSTATE (BB*LL*HH)   // 8 MB per array
#define GRID 128
#define TPB 256

// Physical-slot state; slots are stable, only the merged slot is rewritten.
__device__ float g_h[NSTATE];
__device__ float g_c[NSTATE];
// Pair-compose results keyed by LEFT leaf's physical slot: (b*64+slotL)*512
__device__ float g_nh[NSTATE];
__device__ float g_nc[NSTATE];
__device__ float g_cw[BB*64];    // cw keyed by left slot
__device__ int   g_idx[BB*64];   // logical leaf j -> physical slot
__device__ int2  g_rows[BB*2];   // per batch, up to 2 fresh pair rows {keyL,keyR}; x=-1 invalid
__device__ unsigned g_barrier;   // grid barrier counter (reset each launch)

__device__ __forceinline__ float sigm(float x){ return 1.0f/(1.0f+expf(-x)); }

// packed fp32x2 FMA: 2 MACs/instr (scalar FFMA is half-rate on sm_103a)
__device__ __forceinline__ void ffma2(float2 &acc, float2 a, float2 b){
    asm("fma.rn.f32x2 %0, %1, %2, %0;"
        : "+l"(reinterpret_cast<unsigned long long&>(acc))
        : "l"(reinterpret_cast<unsigned long long&>(a)),
          "l"(reinterpret_cast<unsigned long long&>(b)));
}

// release/acquire grid barrier (all GRID blocks co-resident: 1 block/SM)
__device__ __forceinline__ void grid_barrier(unsigned target){
    __syncthreads();
    if (threadIdx.x == 0){
        asm volatile("red.release.gpu.global.add.u32 [%0], 1;"
                     :: "l"(&g_barrier) : "memory");
        unsigned v;
        do {
            asm volatile("ld.acquire.gpu.global.u32 %0, [%1];"
                         : "=r"(v) : "l"(&g_barrier) : "memory");
        } while (v < target);
    }
    __syncthreads();
}

// ---------------------------------------------------------------------------
// Word GEMM: state = x @ w_word^T + b_word ; h = state[:,:512], c = state[:,512:]
// ---------------------------------------------------------------------------
__global__ __launch_bounds__(256) void word_gemm(
    const float* __restrict__ x, const float* __restrict__ w,
    const float* __restrict__ bias)
{
    __shared__ float As[64][33];
    __shared__ float Ws[64][33];
    int tid = threadIdx.x;
    int tx = tid & 15, ty = tid >> 4;
    int m0 = blockIdx.y * 64;
    int c0 = blockIdx.x * 64;
    float acc[4][4] = {};

    for (int k0 = 0; k0 < 512; k0 += 32) {
        #pragma unroll
        for (int t = tid; t < 64 * 32; t += 256) {
            int r = t >> 5, kk = t & 31;
            As[r][kk] = x[(m0 + r) * 512 + k0 + kk];
            Ws[r][kk] = w[(c0 + r) * 512 + k0 + kk];
        }
        __syncthreads();
        #pragma unroll
        for (int kk = 0; kk < 32; kk++) {
            float a[4], b[4];
            #pragma unroll
            for (int r = 0; r < 4; r++) a[r] = As[ty * 4 + r][kk];
            #pragma unroll
            for (int cc = 0; cc < 4; cc++) b[cc] = Ws[tx * 4 + cc][kk];
            #pragma unroll
            for (int r = 0; r < 4; r++)
                #pragma unroll
                for (int cc = 0; cc < 4; cc++)
                    acc[r][cc] += a[r] * b[cc];
        }
        __syncthreads();
    }
    #pragma unroll
    for (int r = 0; r < 4; r++) {
        int m = m0 + ty * 4 + r;
        #pragma unroll
        for (int cc = 0; cc < 4; cc++) {
            int col = c0 + tx * 4 + cc;
            float v = acc[r][cc] + bias[col];
            if (col < 512) g_h[m * 512 + col] = v;
            else           g_c[m * 512 + col - 512] = v;
        }
    }
}

__global__ void init_state(){
    int t = blockIdx.x * blockDim.x + threadIdx.x;
    if (t < BB * 64) g_idx[t] = t & 63;
    if (t < BB * 2)  g_rows[t] = make_int2(-1, -1);
    if (t == 0)      g_barrier = 0u;
}

// ---------------------------------------------------------------------------
// Full compose for iteration 0: all 63 pairs per batch. f32x2 inner loop.
// ---------------------------------------------------------------------------
__global__ __launch_bounds__(256) void compose_full(
    const float* __restrict__ wcomp, const float* __restrict__ bcomp)
{
    __shared__ float As[128][34];
    __shared__ float Ws[5][8][34];
    const int tid = threadIdx.x;
    const int tx = tid & 7, ty = tid >> 3;
    const int h0 = blockIdx.x * 8;
    const int m0 = blockIdx.y * 128;
    const int M  = BB * NPAIR0;   // 4032

    const int lr = tid >> 5, kkld = tid & 31;
    int abase[16];
    #pragma unroll
    for (int t = 0; t < 16; t++) {
        int row = m0 + lr + 8 * t;
        if (row < M) { int b = row / 63; int j = row - b * 63; abase[t] = (b * 64 + j) * 512; }
        else abase[t] = -1;
    }

    float2 acc[4][5];
    #pragma unroll
    for (int r = 0; r < 4; r++)
        #pragma unroll
        for (int g = 0; g < 5; g++) acc[r][g] = make_float2(0.f, 0.f);

    for (int k0 = 0; k0 < 1024; k0 += 32) {
        #pragma unroll
        for (int t = 0; t < 16; t++)
            As[lr + 8 * t][kkld] = (abase[t] >= 0) ? g_h[abase[t] + k0 + kkld] : 0.f;
        #pragma unroll
        for (int t = 0; t < 5; t++) {
            int idx = tid + 256 * t;
            int g = idx >> 8, rem = idx & 255, hh = rem >> 5, kk = rem & 31;
            Ws[g][hh][kk] = wcomp[(g * 512 + h0 + hh) * 1024 + k0 + kk];
        }
        __syncthreads();
        #pragma unroll
        for (int k2 = 0; k2 < 16; k2++) {
            float2 wv[5];
            #pragma unroll
            for (int g = 0; g < 5; g++) wv[g] = ((const float2*)Ws[g][tx])[k2];
            #pragma unroll
            for (int r = 0; r < 4; r++) {
                float2 av = ((const float2*)As[ty * 4 + r])[k2];
                #pragma unroll
                for (int g = 0; g < 5; g++) ffma2(acc[r][g], av, wv[g]);
            }
        }
        __syncthreads();
    }

    int hg = h0 + tx;
    float bi  = bcomp[hg],        bfl = bcomp[512 + hg], bfr = bcomp[1024 + hg];
    float bu  = bcomp[1536 + hg], bo  = bcomp[2048 + hg];
    #pragma unroll
    for (int r = 0; r < 4; r++) {
        int row = m0 + ty * 4 + r;
        if (row >= M) continue;
        int b = row / 63, j = row - b * 63;
        int base = (b * 64 + j) * 512;
        float cl = g_c[base + hg], cr = g_c[base + 512 + hg];
        float vi  = acc[r][0].x + acc[r][0].y + bi;
        float vfl = acc[r][1].x + acc[r][1].y + bfl + 1.f;
        float vfr = acc[r][2].x + acc[r][2].y + bfr + 1.f;
        float vu  = acc[r][3].x + acc[r][3].y + bu;
        float vo  = acc[r][4].x + acc[r][4].y + bo;
        float cn = cl * sigm(vfl) + cr * sigm(vfr) + tanhf(vu) * sigm(vi);
        float hn = sigm(vo) * tanhf(cn);
        g_nh[base + hg] = hn;
        g_nc[base + hg] = cn;
    }
}

// cw for all initial pair keys (slot j = 0..62)
__global__ __launch_bounds__(256) void cw_full(const float* __restrict__ q){
    int b = blockIdx.x;
    int warp = threadIdx.x >> 5, lane = threadIdx.x & 31;
    for (int j = warp; j < 63; j += 8) {
        const float* row = &g_nh[(b * 64 + j) * 512];
        float s = 0.f;
        #pragma unroll
        for (int t = 0; t < 16; t++) s += row[lane + 32 * t] * q[lane + 32 * t];
        #pragma unroll
        for (int o = 16; o > 0; o >>= 1) s += __shfl_xor_sync(0xffffffffu, s, o);
        if (lane == 0) g_cw[b * 64 + j] = s;
    }
}

// ---------------------------------------------------------------------------
// Persistent loop kernel: 63 iterations of {select, compose} with grid barriers.
// 128 blocks x 256 threads, 1 block/SM (big smem), all co-resident.
// Dynamic smem: Wres[20][1028] + As[128][66] + rinfo[128]
// ---------------------------------------------------------------------------
#define WRES_F   (20*1028)
#define AS_F     (128*66)
#define SMEM_BYTES ((WRES_F + AS_F)*4 + 128*8)

__global__ __launch_bounds__(TPB, 1) void tree_loop(
    const int* __restrict__ length, const float* __restrict__ q,
    const float* __restrict__ wcomp, const float* __restrict__ bcomp,
    float* __restrict__ out)
{
    extern __shared__ float smem[];
    float* Wres = smem;                 // 20 rows (g*4+hh) x 1028 (1024 + pad)
    float* As   = smem + WRES_F;        // 128 rows x 66 (64 + pad)
    int2*  rinfo = (int2*)(smem + WRES_F + AS_F);

    __shared__ int   sh_idx[64];
    __shared__ float sh_cwv[64];
    __shared__ float s_red[8];
    __shared__ int   sh_s;

    const int tid = threadIdx.x;
    const int blk = blockIdx.x;
    const int tx = tid & 3, ty = tid >> 2;
    const int h0 = blk * 4;
    const int lane = tid & 31, warp = tid >> 5;
    const int rowl = tid >> 5, kk2 = tid & 31;   // A-fill role

    // Load resident W slice (20 rows x 1024) once.
    for (int idx = tid; idx < 20 * 1024; idx += TPB) {
        int r = idx >> 10, k = idx & 1023;
        Wres[r * 1028 + k] = wcomp[((r >> 2) * 512 + h0 + (r & 3)) * 1024 + k];
    }
    const int hg = h0 + tx;
    const float bi  = bcomp[hg],        bfl = bcomp[512 + hg], bfr = bcomp[1024 + hg];
    const float bu  = bcomp[1536 + hg], bo  = bcomp[2048 + hg];

    unsigned target = 0;

    for (int i = 0; i < LL - 1; i++) {
        const int n = LL - 1 - i;

        // ================= SELECT phase (blocks 0..63, one per batch) ========
        if (blk < BB) {
            const int b = blk;
            const int len = length[b];
            if (tid < 64) sh_idx[tid] = g_idx[b * 64 + tid];
            __syncthreads();

            if (i > 0) {
                #pragma unroll
                for (int t = 0; t < 2; t++) {
                    int key = g_rows[b * 2 + t].x;      // own block's prior write
                    if (key >= 0) {
                        float s = __ldcg(&g_nh[key * 512 + tid]) * q[tid]
                                + __ldcg(&g_nh[key * 512 + 256 + tid]) * q[256 + tid];
                        #pragma unroll
                        for (int o = 16; o > 0; o >>= 1) s += __shfl_xor_sync(0xffffffffu, s, o);
                        if (lane == 0) s_red[warp] = s;
                        __syncthreads();
                        if (tid == 0) {
                            float tot = 0.f;
                            #pragma unroll
                            for (int w = 0; w < 8; w++) tot += s_red[w];
                            g_cw[key] = tot;
                        }
                        __syncthreads();
                    }
                }
            }
            if (tid < 64) {
                float v = -1e9f;
                if (tid < n && (i + 1 + tid) < len) v = g_cw[b * 64 + sh_idx[tid]];
                sh_cwv[tid] = v;
            }
            __syncthreads();
            if (tid == 0) {
                int s;
                if (i + 1 >= len) s = -2;               // done==0: plain truncation
                else if (n == 1) s = 0;
                else {
                    float best = -2e9f; int bj = 0;
                    for (int j = 0; j < n; j++) {
                        float v = sh_cwv[j];
                        if (v > best) { best = v; bj = j; }
                    }
                    s = bj;
                }
                sh_s = s;
                int2 ra = make_int2(-1, -1), rb = make_int2(-1, -1);
                if (s >= 0 && i < LL - 2) {
                    if (s >= 1)     ra = make_int2(b * 64 + sh_idx[s - 1], b * 64 + sh_idx[s]);
                    if (s <= n - 2) rb = make_int2(b * 64 + sh_idx[s],     b * 64 + sh_idx[s + 2]);
                }
                g_rows[b * 2 + 0] = ra;
                g_rows[b * 2 + 1] = rb;
            }
            __syncthreads();
            int s = sh_s;
            if (s >= 0) {
                int slot = sh_idx[s];
                int base = (b * 64 + slot) * 512;
                float2 vh = __ldcg((const float2*)&g_nh[base + tid * 2]);
                float2 vc = __ldcg((const float2*)&g_nc[base + tid * 2]);
                *(float2*)&g_h[base + tid * 2] = vh;
                *(float2*)&g_c[base + tid * 2] = vc;
                if (tid >= s + 1 && tid <= n - 1) g_idx[b * 64 + tid] = sh_idx[tid + 1];
            }
        }
        target += GRID; grid_barrier(target);

        // ================= COMPOSE phase (all blocks) =========================
        if (i < LL - 2) {
            if (tid < 128) rinfo[tid] = __ldcg(&g_rows[tid]);
            __syncthreads();

            float2 acc[2][5];
            #pragma unroll
            for (int r = 0; r < 2; r++)
                #pragma unroll
                for (int g = 0; g < 5; g++) acc[r][g] = make_float2(0.f, 0.f);

            float2 pv[16];
            // prefetch chunk 0 (k0 = 0 -> left half, base ri.x)
            #pragma unroll
            for (int t = 0; t < 16; t++) {
                int2 ri = rinfo[rowl + 8 * t];
                pv[t] = (ri.x >= 0)
                      ? __ldcg((const float2*)&g_h[ri.x * 512 + kk2 * 2])
                      : make_float2(0.f, 0.f);
            }

            for (int c = 0; c < 16; c++) {
                __syncthreads();       // As consumers of previous chunk done
                #pragma unroll
                for (int t = 0; t < 16; t++)
                    ((float2*)(As + (rowl + 8 * t) * 66))[kk2] = pv[t];
                __syncthreads();
                if (c < 15) {
                    int k0 = (c + 1) * 64;
                    int off = (k0 & 511) + kk2 * 2;
                    #pragma unroll
                    for (int t = 0; t < 16; t++) {
                        int2 ri = rinfo[rowl + 8 * t];
                        int basep = (k0 < 512) ? ri.x : ri.y;
                        pv[t] = (ri.x >= 0)
                              ? __ldcg((const float2*)&g_h[basep * 512 + off])
                              : make_float2(0.f, 0.f);
                    }
                }
                #pragma unroll
                for (int k2 = 0; k2 < 32; k2++) {
                    float2 wv[5];
                    #pragma unroll
                    for (int g = 0; g < 5; g++)
                        wv[g] = ((const float2*)(Wres + (g * 4 + tx) * 1028))[c * 32 + k2];
                    #pragma unroll
                    for (int r = 0; r < 2; r++) {
                        float2 av = ((const float2*)(As + (ty * 2 + r) * 66))[k2];
                        #pragma unroll
                        for (int g = 0; g < 5; g++) ffma2(acc[r][g], av, wv[g]);
                    }
                }
            }

            #pragma unroll
            for (int r = 0; r < 2; r++) {
                int row = ty * 2 + r;
                int2 ri = rinfo[row];
                if (ri.x < 0) continue;
                float cl = __ldcg(&g_c[ri.x * 512 + hg]);
                float cr = __ldcg(&g_c[ri.y * 512 + hg]);
                float vi  = acc[r][0].x + acc[r][0].y + bi;
                float vfl = acc[r][1].x + acc[r][1].y + bfl + 1.f;
                float vfr = acc[r][2].x + acc[r][2].y + bfr + 1.f;
                float vu  = acc[r][3].x + acc[r][3].y + bu;
                float vo  = acc[r][4].x + acc[r][4].y + bo;
                float cn = cl * sigm(vfl) + cr * sigm(vfr) + tanhf(vu) * sigm(vi);
                float hn = sigm(vo) * tanhf(cn);
                g_nh[ri.x * 512 + hg] = hn;
                g_nc[ri.x * 512 + hg] = cn;
            }
        }
        target += GRID; grid_barrier(target);
    }

    // ================= finalize: out = concat(h[:,0,:], c[:,0,:]) =============
    if (blk < BB) {
        int slot = g_idx[blk * 64];
        int base = (blk * 64 + slot) * 512;
        out[blk * 512 + tid]                    = g_h[base + tid];
        out[blk * 512 + 256 + tid]              = g_h[base + 256 + tid];
        out[BB * 512 + blk * 512 + tid]         = g_c[base + tid];
        out[BB * 512 + blk * 512 + 256 + tid]   = g_c[base + 256 + tid];
    }
}

// ---------------------------------------------------------------------------
extern "C" void kernel_launch(void* const* d_in, const int* in_sizes, int n_in,
                              void* d_out, int out_size)
{
    const float* x      = (const float*)d_in[0];
    const int*   length = (const int*)  d_in[1];
    const float* w_word = (const float*)d_in[2];
    const float* b_word = (const float*)d_in[3];
    const float* w_comp = (const float*)d_in[4];
    const float* b_comp = (const float*)d_in[5];
    const float* q      = (const float*)d_in[6];
    float* out = (float*)d_out;

    static int smem_set = 0;
    if (!smem_set) {
        cudaFuncSetAttribute(tree_loop, cudaFuncAttributeMaxDynamicSharedMemorySize,
                             SMEM_BYTES);
        smem_set = 1;
    }

    word_gemm<<<dim3(16, 64), 256>>>(x, w_word, b_word);
    init_state<<<16, 256>>>();
    compose_full<<<dim3(64, 32), 256>>>(w_comp, b_comp);
    cw_full<<<BB, 256>>>(q);
    tree_loop<<<GRID, TPB, SMEM_BYTES>>>(length, q, w_comp, b_comp, out);
}